// round 1
// baseline (speedup 1.0000x reference)
#include <cuda_runtime.h>

// ---------------------------------------------------------------------------
// LocallyGroupedAttn (Twins-SVT window attention), fp32 FFMA baseline.
// B=8, H=W=112, C=256, ws=7, nh=8, hd=32. 112%7==0 -> no padding path.
// Pipeline: qkv_gemm (gathered rows) -> attn per (window,head) -> proj_gemm.
// ---------------------------------------------------------------------------

#define B_    8
#define H_    112
#define W_    112
#define C_    256
#define N_    (H_ * W_)          // 12544
#define WS_   7
#define NH_   8
#define HD_   32
#define GW_   16                 // windows per side (112/7)
#define WS2_  49
#define BW_   (B_ * GW_ * GW_)   // 2048 (batch*windows)
#define M_    (BW_ * WS2_)       // 100352 rows (== B_*N_)

// Scratch (allocation-free contract: __device__ globals).
// Layout for all: [m][C_] with m = bw*49 + t, channel = head*32 + d.
__device__ float g_q[M_ * C_];
__device__ float g_k[M_ * C_];
__device__ float g_v[M_ * C_];
__device__ float g_o[M_ * C_];

// row m = bw*49 + t  ->  flat token index in [B, H, W] spatial order
__device__ __forceinline__ int token_of(int m) {
    int bw  = m / WS2_;
    int t   = m - bw * WS2_;
    int b   = bw >> 8;           // bw / 256
    int win = bw & 255;
    int ty  = t / WS_;
    int tx  = t - ty * WS_;
    int y   = (win >> 4) * WS_ + ty;
    int x   = (win & 15) * WS_ + tx;
    return (b * H_ + y) * W_ + x;
}

// ---------------------------------------------------------------------------
// QKV GEMM: out[m][n] = sum_k xw[m][k] * qkv_w[n][k] + qkv_b[n]
// M=100352 (gathered window rows), N=768, K=256.
// Block tile 128x64, BK=16, 256 threads, 8x4 per thread.
// ---------------------------------------------------------------------------
__global__ __launch_bounds__(256) void qkv_gemm(const float* __restrict__ x,
                                                const float* __restrict__ w,
                                                const float* __restrict__ bias) {
    __shared__ float As[16][128];
    __shared__ float Bs[16][64];
    __shared__ const float* rowp[128];

    const int tid = threadIdx.x;
    const int tx  = tid & 15;
    const int ty  = tid >> 4;
    const int m0  = blockIdx.x * 128;
    const int n0  = blockIdx.y * 64;

    if (tid < 128) rowp[tid] = x + (size_t)token_of(m0 + tid) * C_;
    __syncthreads();

    float acc[8][4];
#pragma unroll
    for (int r = 0; r < 8; r++)
#pragma unroll
        for (int c = 0; c < 4; c++) acc[r][c] = 0.f;

    for (int k0 = 0; k0 < C_; k0 += 16) {
        // A: 128 rows x 16 k = 512 float4; 2 per thread, rows fastest (STS conflict-free)
#pragma unroll
        for (int l = 0; l < 2; l++) {
            int idx = tid + l * 256;
            int kq  = idx >> 7;          // 0..3
            int row = idx & 127;
            const float4 va = *(const float4*)(rowp[row] + k0 + kq * 4);
            As[kq * 4 + 0][row] = va.x;
            As[kq * 4 + 1][row] = va.y;
            As[kq * 4 + 2][row] = va.z;
            As[kq * 4 + 3][row] = va.w;
        }
        // B: 64 n-rows x 16 k = 256 float4; transpose into Bs[k][n]
        {
            int n  = tid >> 2;
            int kq = tid & 3;
            const float4 vb = *(const float4*)(w + (size_t)(n0 + n) * C_ + k0 + kq * 4);
            Bs[kq * 4 + 0][n] = vb.x;
            Bs[kq * 4 + 1][n] = vb.y;
            Bs[kq * 4 + 2][n] = vb.z;
            Bs[kq * 4 + 3][n] = vb.w;
        }
        __syncthreads();
#pragma unroll
        for (int kk = 0; kk < 16; kk++) {
            float a[8], b[4];
#pragma unroll
            for (int r = 0; r < 8; r++) a[r] = As[kk][ty * 8 + r];
#pragma unroll
            for (int c = 0; c < 4; c++) b[c] = Bs[kk][tx * 4 + c];
#pragma unroll
            for (int r = 0; r < 8; r++)
#pragma unroll
                for (int c = 0; c < 4; c++) acc[r][c] = fmaf(a[r], b[c], acc[r][c]);
        }
        __syncthreads();
    }

    // Epilogue: +bias, scatter into q/k/v (part constant per block since 64|256)
    const int nb   = n0 + tx * 4;
    const int part = nb >> 8;
    const int cch  = nb & 255;
    float* dst = (part == 0) ? g_q : (part == 1) ? g_k : g_v;
    const float b0 = bias[nb + 0], b1 = bias[nb + 1], b2 = bias[nb + 2], b3 = bias[nb + 3];
#pragma unroll
    for (int r = 0; r < 8; r++) {
        int m = m0 + ty * 8 + r;
        float4 v;
        v.x = acc[r][0] + b0;
        v.y = acc[r][1] + b1;
        v.z = acc[r][2] + b2;
        v.w = acc[r][3] + b3;
        *(float4*)(dst + (size_t)m * C_ + cch) = v;
    }
}

// ---------------------------------------------------------------------------
// Attention: one block per (window, head). 256 threads.
// S = (Q K^T) * scale ; softmax rows ; O = P V
// smem padded stride 33 for q/k/v (conflict-free), 53 for S.
// ---------------------------------------------------------------------------
__global__ __launch_bounds__(256) void attn_kernel() {
    const int bwh = blockIdx.x;
    const int bw  = bwh >> 3;
    const int h   = bwh & 7;

    __shared__ float qs[52 * 33];
    __shared__ float ks[52 * 33];
    __shared__ float vs[52 * 33];
    __shared__ float S[52 * 53];

    const int tid = threadIdx.x;
    const size_t base = (size_t)bw * WS2_ * C_ + h * HD_;

    for (int idx = tid; idx < WS2_ * HD_; idx += 256) {
        int i = idx >> 5, d = idx & 31;
        qs[i * 33 + d] = g_q[base + (size_t)i * C_ + d];
        ks[i * 33 + d] = g_k[base + (size_t)i * C_ + d];
        vs[i * 33 + d] = g_v[base + (size_t)i * C_ + d];
    }
    // zero the 3 padded rows (49..51) of each tile
    for (int idx = tid; idx < 288; idx += 256) {
        int arr = idx / 96;
        int rem = idx - arr * 96;
        int off = (49 + (rem >> 5)) * 33 + (rem & 31);
        float* p = (arr == 0) ? qs : (arr == 1) ? ks : vs;
        p[off] = 0.f;
    }
    __syncthreads();

    // --- S = Q K^T * scale : 13x13 tiles of 4x4 (covers 52x52 >= 49x49) ---
    const float scale = 0.17677669529663687f;  // 32^-0.5
    if (tid < 169) {
        const int jt = tid % 13, it = tid / 13;
        const int i0 = it * 4, j0 = jt * 4;
        float acc[4][4];
#pragma unroll
        for (int r = 0; r < 4; r++)
#pragma unroll
            for (int c = 0; c < 4; c++) acc[r][c] = 0.f;
#pragma unroll
        for (int d = 0; d < HD_; d++) {
            float a[4], b[4];
#pragma unroll
            for (int r = 0; r < 4; r++) a[r] = qs[(i0 + r) * 33 + d];
#pragma unroll
            for (int c = 0; c < 4; c++) b[c] = ks[(j0 + c) * 33 + d];
#pragma unroll
            for (int r = 0; r < 4; r++)
#pragma unroll
                for (int c = 0; c < 4; c++) acc[r][c] = fmaf(a[r], b[c], acc[r][c]);
        }
#pragma unroll
        for (int r = 0; r < 4; r++)
#pragma unroll
            for (int c = 0; c < 4; c++) S[(i0 + r) * 53 + (j0 + c)] = acc[r][c] * scale;
    }
    __syncthreads();

    // --- softmax over rows 0..48 ---
    if (tid < WS2_) {
        float* row = S + tid * 53;
        float mx = row[0];
#pragma unroll
        for (int j = 1; j < WS2_; j++) mx = fmaxf(mx, row[j]);
        float sum = 0.f;
#pragma unroll
        for (int j = 0; j < WS2_; j++) {
            float e = __expf(row[j] - mx);
            row[j] = e;
            sum += e;
        }
        float inv = __frcp_rn(sum);
#pragma unroll
        for (int j = 0; j < WS2_; j++) row[j] *= inv;
    }
    __syncthreads();

    // --- O = P V : thread handles 2 rows x 4 d-channels ---
    {
        const int txd = tid & 7;   // d-quad: 8*4 = 32
        const int tyy = tid >> 3;  // 0..31, need 25
        if (tyy < 25) {
            const int d0 = txd * 4;
            float acc[2][4];
#pragma unroll
            for (int r = 0; r < 2; r++)
#pragma unroll
                for (int c = 0; c < 4; c++) acc[r][c] = 0.f;
#pragma unroll
            for (int j = 0; j < WS2_; j++) {
                float a0 = S[(tyy * 2 + 0) * 53 + j];
                float a1 = S[(tyy * 2 + 1) * 53 + j];
                float v0 = vs[j * 33 + d0 + 0];
                float v1 = vs[j * 33 + d0 + 1];
                float v2 = vs[j * 33 + d0 + 2];
                float v3 = vs[j * 33 + d0 + 3];
                acc[0][0] = fmaf(a0, v0, acc[0][0]);
                acc[0][1] = fmaf(a0, v1, acc[0][1]);
                acc[0][2] = fmaf(a0, v2, acc[0][2]);
                acc[0][3] = fmaf(a0, v3, acc[0][3]);
                acc[1][0] = fmaf(a1, v0, acc[1][0]);
                acc[1][1] = fmaf(a1, v1, acc[1][1]);
                acc[1][2] = fmaf(a1, v2, acc[1][2]);
                acc[1][3] = fmaf(a1, v3, acc[1][3]);
            }
#pragma unroll
            for (int r = 0; r < 2; r++) {
                int i = tyy * 2 + r;
                if (i < WS2_) {
                    float* o = g_o + (size_t)(bw * WS2_ + i) * C_ + h * HD_ + d0;
                    o[0] = acc[r][0];
                    o[1] = acc[r][1];
                    o[2] = acc[r][2];
                    o[3] = acc[r][3];
                }
            }
        }
    }
}

// ---------------------------------------------------------------------------
// Proj GEMM: out[tok][n] = sum_k g_o[m][k] * proj_w[n][k] + proj_b[n]
// M=100352, N=256, K=256. Same tiling; scatter rows back to spatial order.
// ---------------------------------------------------------------------------
__global__ __launch_bounds__(256) void proj_gemm(const float* __restrict__ w,
                                                 const float* __restrict__ bias,
                                                 float* __restrict__ out) {
    __shared__ float As[16][128];
    __shared__ float Bs[16][64];

    const int tid = threadIdx.x;
    const int tx  = tid & 15;
    const int ty  = tid >> 4;
    const int m0  = blockIdx.x * 128;
    const int n0  = blockIdx.y * 64;

    float acc[8][4];
#pragma unroll
    for (int r = 0; r < 8; r++)
#pragma unroll
        for (int c = 0; c < 4; c++) acc[r][c] = 0.f;

    for (int k0 = 0; k0 < C_; k0 += 16) {
#pragma unroll
        for (int l = 0; l < 2; l++) {
            int idx = tid + l * 256;
            int kq  = idx >> 7;
            int row = idx & 127;
            const float4 va = *(const float4*)(g_o + (size_t)(m0 + row) * C_ + k0 + kq * 4);
            As[kq * 4 + 0][row] = va.x;
            As[kq * 4 + 1][row] = va.y;
            As[kq * 4 + 2][row] = va.z;
            As[kq * 4 + 3][row] = va.w;
        }
        {
            int n  = tid >> 2;
            int kq = tid & 3;
            const float4 vb = *(const float4*)(w + (size_t)(n0 + n) * C_ + k0 + kq * 4);
            Bs[kq * 4 + 0][n] = vb.x;
            Bs[kq * 4 + 1][n] = vb.y;
            Bs[kq * 4 + 2][n] = vb.z;
            Bs[kq * 4 + 3][n] = vb.w;
        }
        __syncthreads();
#pragma unroll
        for (int kk = 0; kk < 16; kk++) {
            float a[8], b[4];
#pragma unroll
            for (int r = 0; r < 8; r++) a[r] = As[kk][ty * 8 + r];
#pragma unroll
            for (int c = 0; c < 4; c++) b[c] = Bs[kk][tx * 4 + c];
#pragma unroll
            for (int r = 0; r < 8; r++)
#pragma unroll
                for (int c = 0; c < 4; c++) acc[r][c] = fmaf(a[r], b[c], acc[r][c]);
        }
        __syncthreads();
    }

    const int nb = n0 + tx * 4;
    const float b0 = bias[nb + 0], b1 = bias[nb + 1], b2 = bias[nb + 2], b3 = bias[nb + 3];
#pragma unroll
    for (int r = 0; r < 8; r++) {
        int m   = m0 + ty * 8 + r;
        int tok = token_of(m);
        float4 v;
        v.x = acc[r][0] + b0;
        v.y = acc[r][1] + b1;
        v.z = acc[r][2] + b2;
        v.w = acc[r][3] + b3;
        *(float4*)(out + (size_t)tok * C_ + nb) = v;
    }
}

// ---------------------------------------------------------------------------
extern "C" void kernel_launch(void* const* d_in, const int* in_sizes, int n_in,
                              void* d_out, int out_size) {
    const float* x      = (const float*)d_in[0];
    const float* qkv_w  = (const float*)d_in[1];
    const float* qkv_b  = (const float*)d_in[2];
    const float* proj_w = (const float*)d_in[3];
    const float* proj_b = (const float*)d_in[4];
    float* out = (float*)d_out;

    dim3 g1(M_ / 128, 768 / 64);
    qkv_gemm<<<g1, 256>>>(x, qkv_w, qkv_b);

    attn_kernel<<<BW_ * NH_, 256>>>();

    dim3 g3(M_ / 128, 256 / 64);
    proj_gemm<<<g3, 256>>>(proj_w, proj_b, out);
}